// round 15
// baseline (speedup 1.0000x reference)
#include <cuda_runtime.h>
#include <math.h>

#define HD   512      // hidden
#define ID   768      // input
#define BB   32       // batch
#define TT   512      // time
#define G4   2048     // 4*HD

// ---------------- f32x2 packed helpers (Blackwell FFMA2) ----------------
__device__ __forceinline__ void ffma2(unsigned long long& d,
                                      unsigned long long a,
                                      unsigned long long b) {
    asm("fma.rn.f32x2 %0, %1, %2, %0;" : "+l"(d) : "l"(a), "l"(b));
}
__device__ __forceinline__ unsigned long long pack2(float lo, float hi) {
    unsigned long long r;
    asm("mov.b64 %0, {%1, %2};" : "=l"(r) : "f"(lo), "f"(hi));
    return r;
}
__device__ __forceinline__ void unpack2(unsigned long long v, float& lo, float& hi) {
    asm("mov.b64 {%0, %1}, %2;" : "=f"(lo), "=f"(hi) : "l"(v));
}

// ---------------- scratch (static device memory; no allocs) ----------------
// gx layout: [t][n][b]  (n = gate*HD + j)  -> coalesced lane=b reads in fwd
__device__ float    g_gx[(size_t)TT * G4 * BB];
// h layout: [buf][k>>2][b][k&3] -> LDG.128 per 4 k at lane-stride 16B (nL=4)
__device__ float    g_hq[2][HD / 4][BB][4];
__device__ unsigned g_bar_count;                  // monotonic arrivals (fwd barrier)
__device__ unsigned g_t_ready[128];               // GEMM brow completion counters

// ---------------- init: reset barrier+flags, seed h with h0[dir=0] ----------------
__global__ void init_kernel(const float* __restrict__ h0)
{
    int idx = blockIdx.x * blockDim.x + threadIdx.x;
    if (idx == 0) g_bar_count = 0;
    if (idx < 128) g_t_ready[idx] = 0u;
    if (idx < BB * HD) {
        int b = idx >> 9;          // /HD
        int k = idx & (HD - 1);
        g_hq[0][k >> 2][b][k & 3] = h0[idx];
    }
}

// ---------------- sync primitives ----------------
__device__ __forceinline__ unsigned ld_relaxed_gpu(const unsigned* p) {
    unsigned v;
    asm volatile("ld.relaxed.gpu.u32 %0, [%1];" : "=r"(v) : "l"(p));
    return v;
}
__device__ __forceinline__ void fence_acqrel_gpu() {
    asm volatile("fence.acq_rel.gpu;" ::: "memory");
}
__device__ __forceinline__ void red_add_relaxed_gpu(unsigned* p, unsigned v) {
    asm volatile("red.relaxed.gpu.global.add.u32 [%0], %1;" :: "l"(p), "r"(v));
}

// ---------------- persistent gx GEMM: 84 CTAs loop brow-major over 4096 tiles ----------------
// ~46KB static SMEM. Launched FIRST (ncu-serialization-safe: completes fully before
// fwd when serialized; under concurrency occupies 84 SMs, fwd gets the other 64.
#define BM 128
#define BN 64
#define BK 16
#define GEMM_CTAS 84
#define N_TILES   (32 * 128)

__global__ __launch_bounds__(256) void gx_gemm_kernel(
    const float* __restrict__ x,     // [B][T][I]
    const float* __restrict__ w,     // [2048][768]
    const float* __restrict__ b1,
    const float* __restrict__ b2)
{
    __shared__ float As[BK][BM + 4];
    __shared__ float Bs[BK][BN + 4];
    __shared__ float St[BM][BN + 1];

    int tid  = threadIdx.x;
    int ty = tid >> 4;
    int tx = tid & 15;
    int lane = tid & 31;
    int wp   = tid >> 5;

    for (int tile = blockIdx.x; tile < N_TILES; tile += GEMM_CTAS) {
        int brow = tile >> 5;    // M tile (4 timesteps)  -- brow-major: early t first
        int bcol = tile & 31;    // N tile

        unsigned long long acc2[4][4];
        #pragma unroll
        for (int i = 0; i < 4; i++)
            #pragma unroll
            for (int j = 0; j < 4; j++) acc2[i][j] = 0ull;

        for (int k0 = 0; k0 < ID; k0 += BK) {
            #pragma unroll
            for (int i = 0; i < 8; i++) {
                int e  = i * 256 + tid;
                int r  = e >> 4;
                int kk = e & 15;
                int m  = brow * BM + r;
                int b  = m & 31, t = m >> 5;
                As[kk][r] = x[((size_t)b * TT + t) * ID + k0 + kk];
            }
            #pragma unroll
            for (int i = 0; i < 4; i++) {
                int e  = i * 256 + tid;
                int n  = e >> 4;
                int kk = e & 15;
                Bs[kk][n] = w[(size_t)(bcol * BN + n) * ID + k0 + kk];
            }
            __syncthreads();

            #pragma unroll
            for (int kk = 0; kk < BK; kk++) {
                ulonglong2 av0 = *(const ulonglong2*)&As[kk][ty * 8];
                ulonglong2 av1 = *(const ulonglong2*)&As[kk][ty * 8 + 4];
                unsigned long long ap[4] = {av0.x, av0.y, av1.x, av1.y};
                float4 bv = *(const float4*)&Bs[kk][tx * 4];
                unsigned long long bsp[4];
                bsp[0] = pack2(bv.x, bv.x);
                bsp[1] = pack2(bv.y, bv.y);
                bsp[2] = pack2(bv.z, bv.z);
                bsp[3] = pack2(bv.w, bv.w);
                #pragma unroll
                for (int ip = 0; ip < 4; ip++)
                    #pragma unroll
                    for (int j = 0; j < 4; j++)
                        ffma2(acc2[ip][j], ap[ip], bsp[j]);
            }
            __syncthreads();
        }

        int ncol = bcol * BN + tx * 4;
        float bias[4];
        #pragma unroll
        for (int j = 0; j < 4; j++) bias[j] = b1[ncol + j] + b2[ncol + j];

        #pragma unroll
        for (int ip = 0; ip < 4; ip++) {
            float lo[4], hi[4];
            #pragma unroll
            for (int j = 0; j < 4; j++) unpack2(acc2[ip][j], lo[j], hi[j]);
            int m0 = ty * 8 + 2 * ip;
            #pragma unroll
            for (int j = 0; j < 4; j++) {
                St[m0][tx * 4 + j]     = lo[j] + bias[j];
                St[m0 + 1][tx * 4 + j] = hi[j] + bias[j];
            }
        }
        __syncthreads();

        #pragma unroll
        for (int round = 0; round < 8; round++) {
            int pair = wp * 32 + round * 4 + (lane >> 3);
            int t_l  = pair >> 6;
            int n_l  = pair & 63;
            int b0   = (lane & 7) * 4;
            float4 v;
            v.x = St[t_l * 32 + b0 + 0][n_l];
            v.y = St[t_l * 32 + b0 + 1][n_l];
            v.z = St[t_l * 32 + b0 + 2][n_l];
            v.w = St[t_l * 32 + b0 + 3][n_l];
            size_t dst = ((size_t)(brow * 4 + t_l) * G4 + (bcol * 64 + n_l)) * BB + b0;
            *(float4*)&g_gx[dst] = v;
        }

        __syncthreads();   // all epilogue reads of St done; safe to reuse SMEM next tile
        if (tid == 0) {
            fence_acqrel_gpu();
            red_add_relaxed_gpu(&g_t_ready[brow], 1u);
        }
    }
}

// ---------------- backward direction: ONE cell step (unchanged) ----------------
__global__ __launch_bounds__(256) void lstm_bwd_step_kernel(
    const float* __restrict__ x,
    const float* __restrict__ h0,
    const float* __restrict__ c0,
    const float* __restrict__ w_ih,
    const float* __restrict__ w_hh,
    const float* __restrict__ b_ih,
    const float* __restrict__ b_hh,
    float* __restrict__ out)
{
    int tid = threadIdx.x;
    int b = tid & 31;
    int j = blockIdx.x * 8 + (tid >> 5);

    float acc[4] = {0.f, 0.f, 0.f, 0.f};
    const float* xrow = x + ((size_t)b * TT + (TT - 1)) * ID;
    #pragma unroll 4
    for (int k = 0; k < ID; k++) {
        float xv = xrow[k];
        #pragma unroll
        for (int g = 0; g < 4; g++)
            acc[g] += xv * w_ih[(size_t)(g * HD + j) * ID + k];
    }
    const float* hrow = h0 + BB * HD + (size_t)b * HD;
    #pragma unroll 4
    for (int k = 0; k < HD; k++) {
        float hv = hrow[k];
        #pragma unroll
        for (int g = 0; g < 4; g++)
            acc[g] += hv * w_hh[(size_t)(g * HD + j) * HD + k];
    }
    #pragma unroll
    for (int g = 0; g < 4; g++) acc[g] += b_ih[g * HD + j] + b_hh[g * HD + j];

    float ig = 1.f / (1.f + __expf(-acc[0]));
    float fg = 1.f / (1.f + __expf(-acc[1]));
    float gg = tanhf(acc[2]);
    float og = 1.f / (1.f + __expf(-acc[3]));
    float c  = fg * c0[BB * HD + (size_t)b * HD + j] + ig * gg;
    float h  = og * tanhf(c);
    out[b * 1024 + 512 + j] = fmaxf(h, 0.f);
}

// ---------------- forward recurrence: 64 CTAs x 512 thr, SM-exclusive via SMEM ----------------
// CTA bx owns units j in [8bx, 8bx+8) -> 32 w_hh rows (r = g*8+u).
// Warp: seg = warp>>1 (64-k window), half = warp&1 (rows half*16..+16). 2-chunk k loop.
// SMEM used 96KB; REQUESTED 192KB so GEMM CTAs (46KB) can never co-reside.
#define SMEM_RESERVE 196608

__device__ __forceinline__ float fsig(float x) {
    return __fdividef(1.f, 1.f + __expf(-x));
}
__device__ __forceinline__ float ftanh(float x) {
    return __fdividef(2.f, 1.f + __expf(-2.f * x)) - 1.f;
}

__global__ __launch_bounds__(512) void lstm_fwd_kernel(
    const float* __restrict__ c0,
    const float* __restrict__ w_hh,   // [2048][512]
    float* __restrict__ out)
{
    extern __shared__ float sm[];
    float* w_s  = sm;                        // [32][512]   r = g*8+u
    float* part = sm + 32 * 512;             // [8 seg][32 r][32 b]

    int tid  = threadIdx.x;
    int bx   = blockIdx.x;       // 0..63
    int lane = tid & 31;
    int warp = tid >> 5;         // 0..15
    int seg  = warp >> 1;        // 0..7   (64-k window)
    int half = warp & 1;         // row half

    // load w_hh slice: local row r -> global row (r>>3)*512 + bx*8 + (r&7)
    for (int i = tid; i < 32 * 128; i += 512) {
        int r  = i >> 7;
        int kq = i & 127;
        int col = (r >> 3) * HD + bx * 8 + (r & 7);
        *(float4*)&w_s[r * HD + kq * 4] =
            *(const float4*)&w_hh[(size_t)col * HD + kq * 4];
    }

    int u = tid >> 5;            // valid for tid<256 (0..7)
    int b = lane;
    int j = bx * 8 + u;
    float c = 0.f, hv = 0.f;
    if (tid < 256) c = c0[(size_t)b * HD + j];

    const float* wrow = w_s + half * 16 * HD;

    __syncthreads();   // w_s ready; g_hq[0] seeded by init kernel

    for (int step = 0; step < TT; step++) {
        int cur = step & 1;

        // ---- gx-ready gate (tid0 only, nanosleep backoff) every 4 steps ----
        if (tid < 256 && (step & 3) == 0) {
            if (tid == 0) {
                if (ld_relaxed_gpu(&g_t_ready[step >> 2]) < 32u) {
                    while (ld_relaxed_gpu(&g_t_ready[step >> 2]) < 32u)
                        __nanosleep(256);
                }
                fence_acqrel_gpu();   // acquire GEMM stores
            }
            asm volatile("bar.sync 2, 256;");
        }

        // ---- gx prefetch (coalesced lane=b), consumed after the sync ----
        float gxv[4];
        if (tid < 256) {
            const float* gp = g_gx + ((size_t)step * G4 + j) * BB + b;
            #pragma unroll
            for (int g = 0; g < 4; g++)
                gxv[g] = __ldcg(gp + (size_t)g * HD * BB);
        }

        // ---- dots: 16 rows x 64 k per warp (2 chunks of 32 k) ----
        unsigned long long acc[16];
        #pragma unroll
        for (int r = 0; r < 16; r++) acc[r] = 0ull;

        #pragma unroll
        for (int chunk = 0; chunk < 2; chunk++) {
            int kbase = seg * 64 + chunk * 32;
            const float4* hsrc = (const float4*)g_hq[cur] + (kbase >> 2) * 32 + lane;
            float4 h4[8];
            #pragma unroll
            for (int i = 0; i < 8; i++)
                h4[i] = __ldcg(hsrc + i * 32);

            #pragma unroll
            for (int it = 0; it < 8; it++) {
                int k = kbase + it * 4;
                unsigned long long ha = pack2(h4[it].x, h4[it].y);
                unsigned long long hb = pack2(h4[it].z, h4[it].w);
                #pragma unroll
                for (int r = 0; r < 16; r++) {
                    ulonglong2 w2 = *(const ulonglong2*)(wrow + r * HD + k);
                    ffma2(acc[r], w2.x, ha);
                    ffma2(acc[r], w2.y, hb);
                }
            }
        }
        #pragma unroll
        for (int r = 0; r < 16; r++) {
            float lo, hi;
            unpack2(acc[r], lo, hi);
            part[(seg * 32 + half * 16 + r) * 32 + lane] = lo + hi;
        }
        __syncthreads();

        // ---- elementwise update: thread (u, b), tid<256 ----
        if (tid < 256) {
            float gate[4];
            #pragma unroll
            for (int g = 0; g < 4; g++) {
                int r = g * 8 + u;
                float s = gxv[g];
                #pragma unroll
                for (int ss = 0; ss < 8; ss++)
                    s += part[(ss * 32 + r) * 32 + b];
                gate[g] = s;
            }
            float ig = fsig(gate[0]);
            float fg = fsig(gate[1]);
            float gg = ftanh(gate[2]);
            float og = fsig(gate[3]);
            c  = fg * c + ig * gg;
            hv = og * ftanh(c);
            // h store: [j>>2][b][j&3] = [2bx + (u>>2)][b][u&3]
            g_hq[1 - cur][2 * bx + (u >> 2)][b][u & 3] = hv;

            asm volatile("bar.sync 1, 256;");   // updaters' h stores done
            if (tid == 0) {
                fence_acqrel_gpu();                       // release h stores
                red_add_relaxed_gpu(&g_bar_count, 1u);    // fire-and-forget
                unsigned target = (unsigned)(step + 1) * 64u;
                if (ld_relaxed_gpu(&g_bar_count) < target) {
                    while (ld_relaxed_gpu(&g_bar_count) < target) { }
                }
                fence_acqrel_gpu();                       // acquire peers' h
            }
        }
        __syncthreads();   // release whole CTA into next step
    }

    if (tid < 256) out[b * 1024 + j] = fmaxf(hv, 0.f);
}

// ---------------- launch: GEMM FIRST (serialization-safe), then fwd, then bwd ----------------
static cudaStream_t s_gemm = 0, s_bwd = 0;
static cudaEvent_t  s_fork = 0, s_join1 = 0, s_join2 = 0;

extern "C" void kernel_launch(void* const* d_in, const int* in_sizes, int n_in,
                              void* d_out, int out_size)
{
    const float* x      = (const float*)d_in[0];
    const float* h0     = (const float*)d_in[1];
    const float* c0     = (const float*)d_in[2];
    const float* w_ih_f = (const float*)d_in[3];
    const float* w_hh_f = (const float*)d_in[4];
    const float* b_ih_f = (const float*)d_in[5];
    const float* b_hh_f = (const float*)d_in[6];
    const float* w_ih_b = (const float*)d_in[7];
    const float* w_hh_b = (const float*)d_in[8];
    const float* b_ih_b = (const float*)d_in[9];
    const float* b_hh_b = (const float*)d_in[10];
    float* out = (float*)d_out;

    if (s_gemm == 0) {   // one-time handle creation (first call pre-capture)
        cudaStreamCreateWithFlags(&s_gemm, cudaStreamNonBlocking);
        cudaStreamCreateWithFlags(&s_bwd,  cudaStreamNonBlocking);
        cudaEventCreateWithFlags(&s_fork,  cudaEventDisableTiming);
        cudaEventCreateWithFlags(&s_join1, cudaEventDisableTiming);
        cudaEventCreateWithFlags(&s_join2, cudaEventDisableTiming);
    }

    cudaFuncSetAttribute(lstm_fwd_kernel,
                         cudaFuncAttributeMaxDynamicSharedMemorySize, SMEM_RESERVE);

    // init on the main (capture) stream: zeroes barrier + ready flags, seeds h
    init_kernel<<<64, 256>>>(h0);

    // fork
    cudaEventRecord(s_fork, 0);
    cudaStreamWaitEvent(s_gemm, s_fork, 0);
    cudaStreamWaitEvent(s_bwd,  s_fork, 0);

    // 1) GEMM stream FIRST: persistent 84-CTA gx producer (brow-major tile order).
    //    Must precede fwd in submission order: ncu serializes kernels, and fwd
    //    polls flags only this kernel sets.
    gx_gemm_kernel<<<GEMM_CTAS, 256, 0, s_gemm>>>(x, w_ih_f, b_ih_f, b_hh_f);

    // 2) main stream: forward recurrence on the remaining 64 SMs (192KB/CTA
    //    excludes GEMM co-residency; 84 + 64 = 148 SMs exactly)
    lstm_fwd_kernel<<<64, 512, SMEM_RESERVE>>>(c0, w_hh_f, out);

    // 3) bwd stream: single backward cell step (independent)
    lstm_bwd_step_kernel<<<64, 256, 0, s_bwd>>>(x, h0, c0, w_ih_b, w_hh_b,
                                                b_ih_b, b_hh_b, out);

    // join
    cudaEventRecord(s_join1, s_gemm);
    cudaStreamWaitEvent(0, s_join1, 0);
    cudaEventRecord(s_join2, s_bwd);
    cudaStreamWaitEvent(0, s_join2, 0);
}

// round 17
// speedup vs baseline: 1.0316x; 1.0316x over previous
#include <cuda_runtime.h>
#include <cuda_bf16.h>
#include <math.h>

#define HD   512      // hidden
#define ID   768      // input
#define BB   32       // batch
#define TT   512      // time
#define G4   2048     // 4*HD

// ---------------- f32x2 packed helpers (Blackwell FFMA2) ----------------
__device__ __forceinline__ void ffma2(unsigned long long& d,
                                      unsigned long long a,
                                      unsigned long long b) {
    asm("fma.rn.f32x2 %0, %1, %2, %0;" : "+l"(d) : "l"(a), "l"(b));
}
__device__ __forceinline__ unsigned long long pack2(float lo, float hi) {
    unsigned long long r;
    asm("mov.b64 %0, {%1, %2};" : "=l"(r) : "f"(lo), "f"(hi));
    return r;
}
__device__ __forceinline__ void unpack2(unsigned long long v, float& lo, float& hi) {
    asm("mov.b64 {%0, %1}, %2;" : "=f"(lo), "=f"(hi) : "l"(v));
}

// ---------------- scratch (static device memory; no allocs) ----------------
__device__ float          g_gx[(size_t)TT * G4 * BB];       // [t][n][b]
__device__ float          g_hq[2][HD / 4][BB][4];           // h ring
__device__ unsigned       g_bar_count;                      // fwd barrier arrivals
__device__ unsigned       g_t_ready[128];                   // GEMM brow counters
__device__ __nv_bfloat16  g_xhi[(size_t)BB * TT * ID];      // bf16 split of x
__device__ __nv_bfloat16  g_xlo[(size_t)BB * TT * ID];
__device__ __nv_bfloat16  g_whi[(size_t)G4 * ID];           // bf16 split of w_ih_f
__device__ __nv_bfloat16  g_wlo[(size_t)G4 * ID];

// ---------------- init: reset barrier+flags, seed h with h0[dir=0] ----------------
__global__ void init_kernel(const float* __restrict__ h0)
{
    int idx = blockIdx.x * blockDim.x + threadIdx.x;
    if (idx == 0) g_bar_count = 0;
    if (idx < 128) g_t_ready[idx] = 0u;
    if (idx < BB * HD) {
        int b = idx >> 9;
        int k = idx & (HD - 1);
        g_hq[0][k >> 2][b][k & 3] = h0[idx];
    }
}

// ---------------- bf16 hi/lo split conversions ----------------
// IMPORTANT: destinations are __device__ symbols referenced from DEVICE code.
// (Passing them as host-side kernel args yields the host shadow address — R16 bug.)
__global__ void conv_x_kernel(const float* __restrict__ src)
{
    const int n = BB * TT * ID;
    for (int i = blockIdx.x * blockDim.x + threadIdx.x; i < n;
         i += gridDim.x * blockDim.x) {
        float v = src[i];
        __nv_bfloat16 h = __float2bfloat16(v);
        g_xhi[i] = h;
        g_xlo[i] = __float2bfloat16(v - __bfloat162float(h));
    }
}
__global__ void conv_w_kernel(const float* __restrict__ src)
{
    const int n = G4 * ID;
    for (int i = blockIdx.x * blockDim.x + threadIdx.x; i < n;
         i += gridDim.x * blockDim.x) {
        float v = src[i];
        __nv_bfloat16 h = __float2bfloat16(v);
        g_whi[i] = h;
        g_wlo[i] = __float2bfloat16(v - __bfloat162float(h));
    }
}

// ---------------- sync primitives ----------------
__device__ __forceinline__ unsigned ld_relaxed_gpu(const unsigned* p) {
    unsigned v;
    asm volatile("ld.relaxed.gpu.u32 %0, [%1];" : "=r"(v) : "l"(p));
    return v;
}
__device__ __forceinline__ void fence_acqrel_gpu() {
    asm volatile("fence.acq_rel.gpu;" ::: "memory");
}
__device__ __forceinline__ void red_add_relaxed_gpu(unsigned* p, unsigned v) {
    asm volatile("red.relaxed.gpu.global.add.u32 [%0], %1;" :: "l"(p), "r"(v));
}

// ---------------- tensor-core gx GEMM: bf16 split, mma.sync.m16n8k16 ----------------
// grid (32, 128): bcol = N tile (64), brow = M tile (128 rows = 4 timesteps x 32 batch)
// 3-term precision: hi*hi + hi*lo + lo*hi, fp32 accum. Transposed epilogue -> g_gx[t][n][b].
#define GBM 128
#define GBN 64
#define GKC 64
#define ASTR 72          // smem row stride in bf16
#define GSMEM_BYTES ((128 + 128 + 64 + 64) * ASTR * 2)   // 55296

__device__ __forceinline__ void mma_bf16(float* c,
    unsigned a0, unsigned a1, unsigned a2, unsigned a3,
    unsigned b0, unsigned b1)
{
    asm("mma.sync.aligned.m16n8k16.row.col.f32.bf16.bf16.f32 "
        "{%0,%1,%2,%3}, {%4,%5,%6,%7}, {%8,%9}, {%0,%1,%2,%3};"
        : "+f"(c[0]), "+f"(c[1]), "+f"(c[2]), "+f"(c[3])
        : "r"(a0), "r"(a1), "r"(a2), "r"(a3), "r"(b0), "r"(b1));
}

__global__ __launch_bounds__(256) void gx_gemm_kernel(
    const float* __restrict__ b1,
    const float* __restrict__ b2)
{
    extern __shared__ char gsm[];
    __nv_bfloat16* Ah = (__nv_bfloat16*)gsm;          // [128][72]
    __nv_bfloat16* Al = Ah + 128 * ASTR;
    __nv_bfloat16* Bh = Al + 128 * ASTR;              // [64][72]
    __nv_bfloat16* Bl = Bh + 64 * ASTR;
    float* St = (float*)gsm;                          // aliased after k-loop: [128][65]
    __shared__ float bias_s[64];

    int tid  = threadIdx.x;
    int bcol = blockIdx.x;   // 0..31
    int brow = blockIdx.y;   // 0..127
    int lane = tid & 31;
    int warp = tid >> 5;     // 0..7
    int warpM = warp & 3;    // 4 M-tiles of 32
    int warpN = warp >> 2;   // 2 N-tiles of 32
    int g  = lane >> 2;      // 0..7
    int tq = lane & 3;       // 0..3

    if (tid < 64) bias_s[tid] = b1[bcol * GBN + tid] + b2[bcol * GBN + tid];

    float acc[2][4][4];
    #pragma unroll
    for (int mt = 0; mt < 2; mt++)
        #pragma unroll
        for (int nt = 0; nt < 4; nt++)
            #pragma unroll
            for (int i = 0; i < 4; i++) acc[mt][nt][i] = 0.f;

    for (int k0 = 0; k0 < ID; k0 += GKC) {
        __syncthreads();   // previous iter's fragment reads done
        // A tiles: 128 rows x 64 (hi+lo); row m -> (b = m&31, t = m>>5)
        for (int i = tid; i < 1024; i += 256) {
            int r = i >> 3, q = i & 7;
            int m = brow * GBM + r;
            int b = m & 31, t = m >> 5;
            size_t src = ((size_t)b * TT + t) * ID + k0 + q * 8;
            *(uint4*)&Ah[r * ASTR + q * 8] = *(const uint4*)&g_xhi[src];
            *(uint4*)&Al[r * ASTR + q * 8] = *(const uint4*)&g_xlo[src];
        }
        // B tiles: 64 rows (n) x 64 (k)
        for (int i = tid; i < 512; i += 256) {
            int r = i >> 3, q = i & 7;
            size_t src = (size_t)(bcol * GBN + r) * ID + k0 + q * 8;
            *(uint4*)&Bh[r * ASTR + q * 8] = *(const uint4*)&g_whi[src];
            *(uint4*)&Bl[r * ASTR + q * 8] = *(const uint4*)&g_wlo[src];
        }
        __syncthreads();

        #pragma unroll
        for (int kk = 0; kk < 4; kk++) {
            int kb = kk * 16 + tq * 2;
            unsigned bh0[4], bh1[4], bl0[4], bl1[4];
            #pragma unroll
            for (int nt = 0; nt < 4; nt++) {
                int n = warpN * 32 + nt * 8 + g;
                bh0[nt] = *(unsigned*)&Bh[n * ASTR + kb];
                bh1[nt] = *(unsigned*)&Bh[n * ASTR + kb + 8];
                bl0[nt] = *(unsigned*)&Bl[n * ASTR + kb];
                bl1[nt] = *(unsigned*)&Bl[n * ASTR + kb + 8];
            }
            #pragma unroll
            for (int mt = 0; mt < 2; mt++) {
                int row = warpM * 32 + mt * 16 + g;
                unsigned ah0 = *(unsigned*)&Ah[row * ASTR + kb];
                unsigned ah1 = *(unsigned*)&Ah[(row + 8) * ASTR + kb];
                unsigned ah2 = *(unsigned*)&Ah[row * ASTR + kb + 8];
                unsigned ah3 = *(unsigned*)&Ah[(row + 8) * ASTR + kb + 8];
                unsigned al0 = *(unsigned*)&Al[row * ASTR + kb];
                unsigned al1 = *(unsigned*)&Al[(row + 8) * ASTR + kb];
                unsigned al2 = *(unsigned*)&Al[row * ASTR + kb + 8];
                unsigned al3 = *(unsigned*)&Al[(row + 8) * ASTR + kb + 8];
                #pragma unroll
                for (int nt = 0; nt < 4; nt++) {
                    mma_bf16(acc[mt][nt], ah0, ah1, ah2, ah3, bh0[nt], bh1[nt]);
                    mma_bf16(acc[mt][nt], ah0, ah1, ah2, ah3, bl0[nt], bl1[nt]);
                    mma_bf16(acc[mt][nt], al0, al1, al2, al3, bh0[nt], bh1[nt]);
                }
            }
        }
    }
    __syncthreads();   // all fragment reads done; St may alias A/B now

    // park acc (+bias) in St[128][65]
    #pragma unroll
    for (int mt = 0; mt < 2; mt++) {
        int row = warpM * 32 + mt * 16 + g;
        #pragma unroll
        for (int nt = 0; nt < 4; nt++) {
            int col = warpN * 32 + nt * 8 + 2 * tq;
            St[row * 65 + col]           = acc[mt][nt][0] + bias_s[col];
            St[row * 65 + col + 1]       = acc[mt][nt][1] + bias_s[col + 1];
            St[(row + 8) * 65 + col]     = acc[mt][nt][2] + bias_s[col];
            St[(row + 8) * 65 + col + 1] = acc[mt][nt][3] + bias_s[col + 1];
        }
    }
    __syncthreads();

    // transposed write: g_gx[t][n][b], dense 512B per warp-instruction
    #pragma unroll
    for (int round = 0; round < 8; round++) {
        int pair = warp * 32 + round * 4 + (lane >> 3);
        int t_l  = pair >> 6;
        int n_l  = pair & 63;
        int b0   = (lane & 7) * 4;
        float4 v;
        v.x = St[(t_l * 32 + b0 + 0) * 65 + n_l];
        v.y = St[(t_l * 32 + b0 + 1) * 65 + n_l];
        v.z = St[(t_l * 32 + b0 + 2) * 65 + n_l];
        v.w = St[(t_l * 32 + b0 + 3) * 65 + n_l];
        size_t dst = ((size_t)(brow * 4 + t_l) * G4 + (bcol * 64 + n_l)) * BB + b0;
        *(float4*)&g_gx[dst] = v;
    }

    __syncthreads();
    if (tid == 0) {
        fence_acqrel_gpu();
        red_add_relaxed_gpu(&g_t_ready[brow], 1u);
    }
}

// ---------------- backward direction: ONE cell step (unchanged) ----------------
__global__ __launch_bounds__(256) void lstm_bwd_step_kernel(
    const float* __restrict__ x,
    const float* __restrict__ h0,
    const float* __restrict__ c0,
    const float* __restrict__ w_ih,
    const float* __restrict__ w_hh,
    const float* __restrict__ b_ih,
    const float* __restrict__ b_hh,
    float* __restrict__ out)
{
    int tid = threadIdx.x;
    int b = tid & 31;
    int j = blockIdx.x * 8 + (tid >> 5);

    float acc[4] = {0.f, 0.f, 0.f, 0.f};
    const float* xrow = x + ((size_t)b * TT + (TT - 1)) * ID;
    #pragma unroll 4
    for (int k = 0; k < ID; k++) {
        float xv = xrow[k];
        #pragma unroll
        for (int g = 0; g < 4; g++)
            acc[g] += xv * w_ih[(size_t)(g * HD + j) * ID + k];
    }
    const float* hrow = h0 + BB * HD + (size_t)b * HD;
    #pragma unroll 4
    for (int k = 0; k < HD; k++) {
        float hv = hrow[k];
        #pragma unroll
        for (int g = 0; g < 4; g++)
            acc[g] += hv * w_hh[(size_t)(g * HD + j) * HD + k];
    }
    #pragma unroll
    for (int g = 0; g < 4; g++) acc[g] += b_ih[g * HD + j] + b_hh[g * HD + j];

    float ig = 1.f / (1.f + __expf(-acc[0]));
    float fg = 1.f / (1.f + __expf(-acc[1]));
    float gg = tanhf(acc[2]);
    float og = 1.f / (1.f + __expf(-acc[3]));
    float c  = fg * c0[BB * HD + (size_t)b * HD + j] + ig * gg;
    float h  = og * tanhf(c);
    out[b * 1024 + 512 + j] = fmaxf(h, 0.f);
}

// ---------------- forward recurrence (exact R12: 128 CTAs, tid0 gx gate) ----------------
#define SMEM_FLOATS (16*512 + 16*16*32)
#define SMEM_BYTES  (SMEM_FLOATS * 4)

__device__ __forceinline__ float fsig(float x) {
    return __fdividef(1.f, 1.f + __expf(-x));
}
__device__ __forceinline__ float ftanh(float x) {
    return __fdividef(2.f, 1.f + __expf(-2.f * x)) - 1.f;
}

__global__ __launch_bounds__(512) void lstm_fwd_kernel(
    const float* __restrict__ c0,
    const float* __restrict__ w_hh,   // [2048][512]
    float* __restrict__ out)
{
    extern __shared__ float sm[];
    float* w_s  = sm;                        // [16][512]   r = g*4+u
    float* part = sm + 16 * 512;             // [16 seg][16 r][32 b]

    int tid  = threadIdx.x;
    int bx   = blockIdx.x;       // 0..127
    int lane = tid & 31;
    int seg  = tid >> 5;         // k-segment 0..15

    for (int i = tid; i < 16 * 128; i += 512) {
        int r  = i >> 7;
        int kq = i & 127;
        int col = (r >> 2) * HD + bx * 4 + (r & 3);
        *(float4*)&w_s[r * HD + kq * 4] =
            *(const float4*)&w_hh[(size_t)col * HD + kq * 4];
    }

    int u = tid >> 5;            // valid for tid<128 (0..3)
    int b = lane;
    int j = bx * 4 + u;
    float c = 0.f, hv = 0.f;
    if (tid < 128) c = c0[(size_t)b * HD + j];

    const float* wseg = w_s + seg * 32;

    __syncthreads();   // w_s ready; g_hq[0] seeded by init kernel

    for (int step = 0; step < TT; step++) {
        int cur = step & 1;

        // ---- h for this warp's k-window: 8x LDG.128, dense (nL=4) ----
        const float4* hsrc = (const float4*)g_hq[cur] + seg * 8 * 32 + lane;
        float4 h4[8];
        #pragma unroll
        for (int i = 0; i < 8; i++)
            h4[i] = __ldcg(hsrc + i * 32);

        // ---- gx-ready gate (tid0 only, nanosleep backoff) every 4 steps ----
        if (tid < 128) {
            if ((step & 3) == 0) {
                if (tid == 0) {
                    if (ld_relaxed_gpu(&g_t_ready[step >> 2]) < 32u) {
                        while (ld_relaxed_gpu(&g_t_ready[step >> 2]) < 32u)
                            __nanosleep(256);
                    }
                    fence_acqrel_gpu();   // acquire GEMM stores
                }
                asm volatile("bar.sync 2, 128;");
            }
        }

        // ---- gx prefetch (coalesced lane=b), consumed after the sync ----
        float gxv[4];
        if (tid < 128) {
            const float* gp = g_gx + ((size_t)step * G4 + j) * BB + b;
            #pragma unroll
            for (int g = 0; g < 4; g++)
                gxv[g] = __ldcg(gp + (size_t)g * HD * BB);
        }

        // ---- dots: 16 rows x 32 k, w broadcast from SMEM, h in regs ----
        unsigned long long acc[16];
        #pragma unroll
        for (int r = 0; r < 16; r++) acc[r] = 0ull;

        #pragma unroll
        for (int it = 0; it < 8; it++) {
            int k = it * 4;
            unsigned long long ha = pack2(h4[it].x, h4[it].y);
            unsigned long long hb = pack2(h4[it].z, h4[it].w);
            #pragma unroll
            for (int r = 0; r < 16; r++) {
                ulonglong2 w2 = *(const ulonglong2*)(wseg + r * HD + k);
                ffma2(acc[r], w2.x, ha);
                ffma2(acc[r], w2.y, hb);
            }
        }
        #pragma unroll
        for (int r = 0; r < 16; r++) {
            float lo, hi;
            unpack2(acc[r], lo, hi);
            part[(seg * 16 + r) * 32 + lane] = lo + hi;
        }
        __syncthreads();

        // ---- elementwise update: thread (u, b), tid<128 ----
        if (tid < 128) {
            float gate[4];
            #pragma unroll
            for (int g = 0; g < 4; g++) {
                int r = g * 4 + u;
                float s = gxv[g];
                #pragma unroll
                for (int ss = 0; ss < 16; ss++)
                    s += part[(ss * 16 + r) * 32 + b];
                gate[g] = s;
            }
            float ig = fsig(gate[0]);
            float fg = fsig(gate[1]);
            float gg = ftanh(gate[2]);
            float og = fsig(gate[3]);
            c  = fg * c + ig * gg;
            hv = og * ftanh(c);
            g_hq[1 - cur][bx][b][u] = hv;    // coalesced: 4 lines/warp

            asm volatile("bar.sync 1, 128;");
            if (tid == 0) {
                fence_acqrel_gpu();
                red_add_relaxed_gpu(&g_bar_count, 1u);
                unsigned target = (unsigned)(step + 1) * 128u;
                if (ld_relaxed_gpu(&g_bar_count) < target) {
                    while (ld_relaxed_gpu(&g_bar_count) < target) { }
                }
                fence_acqrel_gpu();
            }
        }
        __syncthreads();
    }

    if (tid < 128) out[b * 1024 + j] = fmaxf(hv, 0.f);
}

// ---------------- launch: conv+GEMM (side) BEFORE fwd (main); bwd independent ----------------
static cudaStream_t s_gemm = 0, s_bwd = 0;
static cudaEvent_t  s_fork = 0, s_join1 = 0, s_join2 = 0;

extern "C" void kernel_launch(void* const* d_in, const int* in_sizes, int n_in,
                              void* d_out, int out_size)
{
    const float* x      = (const float*)d_in[0];
    const float* h0     = (const float*)d_in[1];
    const float* c0     = (const float*)d_in[2];
    const float* w_ih_f = (const float*)d_in[3];
    const float* w_hh_f = (const float*)d_in[4];
    const float* b_ih_f = (const float*)d_in[5];
    const float* b_hh_f = (const float*)d_in[6];
    const float* w_ih_b = (const float*)d_in[7];
    const float* w_hh_b = (const float*)d_in[8];
    const float* b_ih_b = (const float*)d_in[9];
    const float* b_hh_b = (const float*)d_in[10];
    float* out = (float*)d_out;

    if (s_gemm == 0) {
        cudaStreamCreateWithFlags(&s_gemm, cudaStreamNonBlocking);
        cudaStreamCreateWithFlags(&s_bwd,  cudaStreamNonBlocking);
        cudaEventCreateWithFlags(&s_fork,  cudaEventDisableTiming);
        cudaEventCreateWithFlags(&s_join1, cudaEventDisableTiming);
        cudaEventCreateWithFlags(&s_join2, cudaEventDisableTiming);
    }

    cudaFuncSetAttribute(lstm_fwd_kernel,
                         cudaFuncAttributeMaxDynamicSharedMemorySize, SMEM_BYTES);
    cudaFuncSetAttribute(gx_gemm_kernel,
                         cudaFuncAttributeMaxDynamicSharedMemorySize, GSMEM_BYTES);

    // init on the main (capture) stream
    init_kernel<<<64, 256>>>(h0);

    // fork
    cudaEventRecord(s_fork, 0);
    cudaStreamWaitEvent(s_gemm, s_fork, 0);
    cudaStreamWaitEvent(s_bwd,  s_fork, 0);

    // side stream, BEFORE fwd in submission order (ncu-serialization-safe):
    // bf16 splits (device-symbol destinations), then the tensor-core GEMM
    conv_x_kernel<<<2048, 256, 0, s_gemm>>>(x);
    conv_w_kernel<<<512, 256, 0, s_gemm>>>(w_ih_f);
    dim3 gg(32, 128);
    gx_gemm_kernel<<<gg, 256, GSMEM_BYTES, s_gemm>>>(b_ih_f, b_hh_f);

    // main stream: forward recurrence, concurrent with the GEMM (tensor pipe)
    lstm_fwd_kernel<<<128, 512, SMEM_BYTES>>>(c0, w_hh_f, out);

    // bwd stream: single backward cell step
    lstm_bwd_step_kernel<<<64, 256, 0, s_bwd>>>(x, h0, c0, w_ih_b, w_hh_b,
                                                b_ih_b, b_hh_b, out);

    // join
    cudaEventRecord(s_join1, s_gemm);
    cudaStreamWaitEvent(0, s_join1, 0);
    cudaEventRecord(s_join2, s_bwd);
    cudaStreamWaitEvent(0, s_join2, 0);
}